// round 2
// baseline (speedup 1.0000x reference)
#include <cuda_runtime.h>
#include <cuda_bf16.h>

// Problem constants
#define NW   8192
#define NTOK 64
#define CDIM 180
#define HEADS 6
#define HD   30
#define NW_PER_IMG 1024

// Scratch (allocation-guard-safe: __device__ globals)
__device__ float g_qkv[(long long)NW * NTOK * (3 * CDIM)];   // [nW*N, 540]
__device__ float g_att[(long long)NW * NTOK * CDIM];         // [nW*N, 180]

// ---------------------------------------------------------------------------
// SGEMM (TN): C[M,N] = A[M,K] @ B[N,K]^T + bias[N]
// A row-major [M,K], B row-major [N,K]. M % 64 == 0 assumed. N,K arbitrary.
// 64x64 tile, BK=32, 256 threads, 4x4 register tile.
// ---------------------------------------------------------------------------
#define BM 64
#define BN 64
#define BKK 32

__global__ __launch_bounds__(256) void sgemm_tn(
    const float* __restrict__ A, const float* __restrict__ B,
    const float* __restrict__ bias, float* __restrict__ C,
    int M, int N, int K)
{
    __shared__ float As[BKK][BM];
    __shared__ float Bs[BKK][BN];

    const int tid = threadIdx.x;
    const int tx = tid & 15;          // 0..15 -> 4 cols each
    const int ty = tid >> 4;          // 0..15 -> 4 rows each
    const long long row0 = (long long)blockIdx.y * BM;
    const int col0 = blockIdx.x * BN;

    float acc[4][4];
#pragma unroll
    for (int i = 0; i < 4; i++)
#pragma unroll
        for (int j = 0; j < 4; j++) acc[i][j] = 0.f;

    for (int k0 = 0; k0 < K; k0 += BKK) {
        // Load A tile (64 rows x 32 k) and B tile, 2 float4 each per thread.
#pragma unroll
        for (int r = 0; r < 2; r++) {
            int v  = tid + r * 256;   // 0..511
            int m  = v >> 3;          // row within tile
            int k  = (v & 7) * 4;     // k offset within tile

            float4 a4;
            if (k0 + k + 3 < K) {
                a4 = *(const float4*)(A + (row0 + m) * K + k0 + k);
            } else {
                float t0 = (k0 + k + 0 < K) ? A[(row0 + m) * K + k0 + k + 0] : 0.f;
                float t1 = (k0 + k + 1 < K) ? A[(row0 + m) * K + k0 + k + 1] : 0.f;
                float t2 = (k0 + k + 2 < K) ? A[(row0 + m) * K + k0 + k + 2] : 0.f;
                float t3 = (k0 + k + 3 < K) ? A[(row0 + m) * K + k0 + k + 3] : 0.f;
                a4 = make_float4(t0, t1, t2, t3);
            }
            As[k + 0][m] = a4.x; As[k + 1][m] = a4.y;
            As[k + 2][m] = a4.z; As[k + 3][m] = a4.w;

            int coln = col0 + m;
            float4 b4 = make_float4(0.f, 0.f, 0.f, 0.f);
            if (coln < N) {
                if (k0 + k + 3 < K) {
                    b4 = *(const float4*)(B + (long long)coln * K + k0 + k);
                } else {
                    float t0 = (k0 + k + 0 < K) ? B[(long long)coln * K + k0 + k + 0] : 0.f;
                    float t1 = (k0 + k + 1 < K) ? B[(long long)coln * K + k0 + k + 1] : 0.f;
                    float t2 = (k0 + k + 2 < K) ? B[(long long)coln * K + k0 + k + 2] : 0.f;
                    float t3 = (k0 + k + 3 < K) ? B[(long long)coln * K + k0 + k + 3] : 0.f;
                    b4 = make_float4(t0, t1, t2, t3);
                }
            }
            Bs[k + 0][m] = b4.x; Bs[k + 1][m] = b4.y;
            Bs[k + 2][m] = b4.z; Bs[k + 3][m] = b4.w;
        }
        __syncthreads();

#pragma unroll
        for (int kk = 0; kk < BKK; kk++) {
            float4 a4 = *(const float4*)&As[kk][ty * 4];
            float4 b4 = *(const float4*)&Bs[kk][tx * 4];
            float a[4] = {a4.x, a4.y, a4.z, a4.w};
            float b[4] = {b4.x, b4.y, b4.z, b4.w};
#pragma unroll
            for (int i = 0; i < 4; i++)
#pragma unroll
                for (int j = 0; j < 4; j++)
                    acc[i][j] = fmaf(a[i], b[j], acc[i][j]);
        }
        __syncthreads();
    }

#pragma unroll
    for (int i = 0; i < 4; i++) {
        long long row = row0 + ty * 4 + i;
#pragma unroll
        for (int j = 0; j < 4; j++) {
            int col = col0 + tx * 4 + j;
            if (col < N) C[row * N + col] = acc[i][j] + bias[col];
        }
    }
}

// ---------------------------------------------------------------------------
// Attention core: one block per (window, head), 64 threads = 1 query row each.
// qkv layout [w*64+n][c], c: q at h*30+d, k at 180+h*30+d, v at 360+h*30+d.
// ---------------------------------------------------------------------------
__global__ __launch_bounds__(64) void attn_kernel(
    const float* __restrict__ qkv, const float* __restrict__ mask,
    const float* __restrict__ rpb, float* __restrict__ out)
{
    const int w = blockIdx.x;      // window
    const int h = blockIdx.y;      // head
    const int n = threadIdx.x;     // query token

    __shared__ float ks[NTOK][32];
    __shared__ float vs[NTOK][32];

    const float scale = rsqrtf((float)HD);
    const long long base = (long long)(w * NTOK + n) * (3 * CDIM);

    const float* krow = qkv + base + CDIM + h * HD;
    const float* vrow = qkv + base + 2 * CDIM + h * HD;
#pragma unroll
    for (int d = 0; d < HD; d++) { ks[n][d] = krow[d]; vs[n][d] = vrow[d]; }
    ks[n][30] = 0.f; ks[n][31] = 0.f;
    vs[n][30] = 0.f; vs[n][31] = 0.f;

    float q[32];
    const float* qrow = qkv + base + h * HD;
#pragma unroll
    for (int d = 0; d < HD; d++) q[d] = qrow[d] * scale;
    q[30] = 0.f; q[31] = 0.f;

    __syncthreads();

    const int i1 = n >> 3, j1 = n & 7;
    const int wi = w & (NW_PER_IMG - 1);
    const float* mrow = mask + ((long long)wi * NTOK + n) * NTOK;

    float s[NTOK];
    float mx = -1e30f;
#pragma unroll
    for (int m = 0; m < NTOK; m++) {
        float acc = 0.f;
#pragma unroll
        for (int dq = 0; dq < 8; dq++) {
            float4 k4 = *(const float4*)&ks[m][dq * 4];
            acc = fmaf(q[dq * 4 + 0], k4.x, acc);
            acc = fmaf(q[dq * 4 + 1], k4.y, acc);
            acc = fmaf(q[dq * 4 + 2], k4.z, acc);
            acc = fmaf(q[dq * 4 + 3], k4.w, acc);
        }
        int i2 = m >> 3, j2 = m & 7;
        int idx = (i1 - i2 + 7) * 15 + (j1 - j2 + 7);
        acc += rpb[idx * HEADS + h] + mrow[m];
        s[m] = acc;
        mx = fmaxf(mx, acc);
    }

    float sum = 0.f;
#pragma unroll
    for (int m = 0; m < NTOK; m++) {
        s[m] = __expf(s[m] - mx);
        sum += s[m];
    }
    const float inv = 1.f / sum;

    float o[32];
#pragma unroll
    for (int d = 0; d < 32; d++) o[d] = 0.f;
#pragma unroll
    for (int m = 0; m < NTOK; m++) {
        float p = s[m];
#pragma unroll
        for (int dq = 0; dq < 8; dq++) {
            float4 v4 = *(const float4*)&vs[m][dq * 4];
            o[dq * 4 + 0] = fmaf(p, v4.x, o[dq * 4 + 0]);
            o[dq * 4 + 1] = fmaf(p, v4.y, o[dq * 4 + 1]);
            o[dq * 4 + 2] = fmaf(p, v4.z, o[dq * 4 + 2]);
            o[dq * 4 + 3] = fmaf(p, v4.w, o[dq * 4 + 3]);
        }
    }

    float* orow = out + (long long)(w * NTOK + n) * CDIM + h * HD;
#pragma unroll
    for (int d = 0; d < HD; d++) orow[d] = o[d] * inv;
}

// ---------------------------------------------------------------------------
extern "C" void kernel_launch(void* const* d_in, const int* in_sizes, int n_in,
                              void* d_out, int out_size)
{
    const float* x      = (const float*)d_in[0];
    const float* mask   = (const float*)d_in[1];
    const float* qkv_w  = (const float*)d_in[2];
    const float* qkv_b  = (const float*)d_in[3];
    const float* proj_w = (const float*)d_in[4];
    const float* proj_b = (const float*)d_in[5];
    const float* rpb    = (const float*)d_in[6];
    float* out = (float*)d_out;

    void* p_qkv = nullptr;
    void* p_att = nullptr;
    cudaGetSymbolAddress(&p_qkv, g_qkv);
    cudaGetSymbolAddress(&p_att, g_att);
    float* qkv = (float*)p_qkv;
    float* att = (float*)p_att;

    const int M = NW * NTOK;             // 524288

    // 1) QKV projection: [M,180] @ [540,180]^T + b -> [M,540]
    {
        dim3 grid((3 * CDIM + BN - 1) / BN, M / BM);
        sgemm_tn<<<grid, 256>>>(x, qkv_w, qkv_b, qkv, M, 3 * CDIM, CDIM);
    }

    // 2) Attention per (window, head)
    {
        dim3 grid(NW, HEADS);
        attn_kernel<<<grid, NTOK>>>(qkv, mask, rpb, att);
    }

    // 3) Output projection: [M,180] @ [180,180]^T + b -> [M,180]
    {
        dim3 grid((CDIM + BN - 1) / BN, M / BM);
        sgemm_tn<<<grid, 256>>>(att, proj_w, proj_b, out, M, CDIM, CDIM);
    }
}